// round 17
// baseline (speedup 1.0000x reference)
#include <cuda_runtime.h>
#include <cstdint>

#define BROWS 2048
#define NCOLS 16384
#define NTH 512
#define GRID 148
#define PAIRSTEP 296           /* 148 CTAs x 2 rows per pair */
#define SHIFT 20.0f

#define KNA 0                  /* 64 KB: row-A khot (negated); head doubles as stage for units 6-7 */
#define KNB 65536              /* 64 KB: row-B khot (negated) */
#define STG 131072             /* 96 KB: units 0-5 staging (shared A/B alternately) */
#define DYN_SMEM 229376        /* 224 KB */

// ---- packed f32x2 helpers ----
__device__ __forceinline__ uint64_t pk2(float lo, float hi) {
    uint64_t r; asm("mov.b64 %0,{%1,%2};" : "=l"(r) : "f"(lo), "f"(hi)); return r;
}
__device__ __forceinline__ void upk2(uint64_t v, float& lo, float& hi) {
    asm("mov.b64 {%0,%1},%2;" : "=f"(lo), "=f"(hi) : "l"(v));
}
__device__ __forceinline__ uint64_t mul2(uint64_t a, uint64_t b) {
    uint64_t r; asm("mul.rn.f32x2 %0,%1,%2;" : "=l"(r) : "l"(a), "l"(b)); return r;
}
__device__ __forceinline__ uint64_t add2(uint64_t a, uint64_t b) {
    uint64_t r; asm("add.rn.f32x2 %0,%1,%2;" : "=l"(r) : "l"(a), "l"(b)); return r;
}
__device__ __forceinline__ uint64_t fma2(uint64_t a, uint64_t b, uint64_t c) {
    uint64_t r; asm("fma.rn.f32x2 %0,%1,%2,%3;" : "=l"(r) : "l"(a), "l"(b), "l"(c)); return r;
}
__device__ __forceinline__ uint32_t smem_u32(const void* p) {
    uint32_t a; asm("{ .reg .u64 t; cvta.to.shared.u64 t, %1; cvt.u32.u64 %0, t; }" : "=r"(a) : "l"(p));
    return a;
}
__device__ __forceinline__ void bulk_g2s(uint32_t dst, const void* gsrc, uint32_t bytes, uint32_t mbar) {
    asm volatile("cp.async.bulk.shared::cta.global.mbarrier::complete_tx::bytes [%0], [%1], %2, [%3];"
                 :: "r"(dst), "l"(gsrc), "r"(bytes), "r"(mbar) : "memory");
}
__device__ __forceinline__ void mbar_init(uint32_t mbar, uint32_t cnt) {
    asm volatile("mbarrier.init.shared.b64 [%0], %1;" :: "r"(mbar), "r"(cnt) : "memory");
}
__device__ __forceinline__ void mbar_expect_tx(uint32_t mbar, uint32_t bytes) {
    asm volatile("mbarrier.arrive.expect_tx.shared.b64 _, [%0], %1;" :: "r"(mbar), "r"(bytes) : "memory");
}
__device__ __forceinline__ void mbar_wait(uint32_t mbar, uint32_t parity) {
    asm volatile(
        "{\n\t.reg .pred P;\n\t"
        "WL_%=:\n\t"
        "mbarrier.try_wait.parity.acquire.cta.shared::cta.b64 P, [%0], %1, 0x989680;\n\t"
        "@P bra.uni WD_%=;\n\t"
        "bra.uni WL_%=;\n\t"
        "WD_%=:\n\t}"
        :: "r"(mbar), "r"(parity) : "memory");
}

extern __shared__ char dynbuf[];

// Consume one 2048-elem unit (absolute smem offsets) -> E regs + SnP/QnP acc.
#define CONS(E, u, AO, BO)                                                    \
    do {                                                                      \
        float4 a = *reinterpret_cast<const float4*>(dynbuf + (AO) + tid * 16);\
        float4 b = *reinterpret_cast<const float4*>(dynbuf + (BO) + tid * 16);\
        float q0 = __expf(a.x + b.x - SHIFT);                                 \
        float q1 = __expf(a.y + b.y - SHIFT);                                 \
        float q2 = __expf(a.z + b.z - SHIFT);                                 \
        float q3 = __expf(a.w + b.w - SHIFT);                                 \
        uint64_t p0 = pk2(q0, q1), p1 = pk2(q2, q3);                          \
        E[2 * (u)]     = p0;                                                  \
        E[2 * (u) + 1] = p1;                                                  \
        SnP = add2(SnP, p0); SnP = add2(SnP, p1);                             \
        QnP = fma2(p0, p0, QnP); QnP = fma2(p1, p1, QnP);                     \
    } while (0)

// units 0-5 from STG, 6-7 from KNX head
#define PROLOGUE(E, KNX)                                                      \
    do {                                                                      \
        CONS(E, 0, STG + 0,     STG + 49152 + 0);                             \
        CONS(E, 1, STG + 8192,  STG + 49152 + 8192);                          \
        CONS(E, 2, STG + 16384, STG + 49152 + 16384);                         \
        CONS(E, 3, STG + 24576, STG + 49152 + 24576);                         \
        CONS(E, 4, STG + 32768, STG + 49152 + 32768);                         \
        CONS(E, 5, STG + 40960, STG + 49152 + 40960);                         \
        CONS(E, 6, (KNX) + 0,    (KNX) + 16384);                              \
        CONS(E, 7, (KNX) + 8192, (KNX) + 16384 + 8192);                       \
    } while (0)

// Reduction split in two phases so the OTHER row's APPLY fills the gap.
#define REDB(Sv, Qv, RB)                                                      \
    do {                                                                      \
        float s1 = (Sv), q1 = (Qv);                                           \
        _Pragma("unroll")                                                     \
        for (int o = 16; o; o >>= 1) {                                        \
            s1 += __shfl_xor_sync(0xffffffffu, s1, o);                        \
            q1 += __shfl_xor_sync(0xffffffffu, q1, o);                        \
        }                                                                     \
        if (l == 0) RB[w] = make_float2(s1, q1);                              \
        __syncthreads();                                                      \
    } while (0)

#define REDE(RB, i0v, i1v)                                                    \
    do {                                                                      \
        uint4 pv = *reinterpret_cast<const uint4*>(&RB[(l & 7) * 2]);         \
        float Sb = __uint_as_float(pv.x) + __uint_as_float(pv.z);             \
        float Qb = __uint_as_float(pv.y) + __uint_as_float(pv.w);             \
        _Pragma("unroll")                                                     \
        for (int o = 4; o; o >>= 1) {                                         \
            Sb += __shfl_xor_sync(0xffffffffu, Sb, o);                        \
            Qb += __shfl_xor_sync(0xffffffffu, Qb, o);                        \
        }                                                                     \
        (i0v) = __fdividef(c, Sb);                                            \
        float u_ = fmaf(Sb, Sb, -(c * Qb));                                   \
        u_ = fmaxf(u_, 1e-30f);                                               \
        (i1v) = __fdividef(c * Sb, u_);   /* c/S1, independent of i0 chain */ \
    } while (0)

// One 2-iteration apply; kn (negated khot) RMW in smem. WO=1: write-only.
#define APPLY(E, i0v, i1v, KOFF, WO, DOACC, Sv, Qv)                           \
    do {                                                                      \
        const uint64_t ninv0 = pk2(-(i0v), -(i0v));                           \
        const uint64_t ninv1 = pk2(-(i1v), -(i1v));                           \
        uint64_t accS = 0ULL, accQ = 0ULL;                                    \
        _Pragma("unroll")                                                     \
        for (int s = 0; s < 8; s++) {                                         \
            uint64_t a0 = mul2(E[2*s], ninv0);                                \
            E[2*s]   = fma2(a0, E[2*s], E[2*s]);                              \
            uint64_t a1 = mul2(E[2*s+1], ninv0);                              \
            E[2*s+1] = fma2(a1, E[2*s+1], E[2*s+1]);                          \
            uint64_t b0 = mul2(E[2*s], ninv1);                                \
            E[2*s]   = fma2(b0, E[2*s], E[2*s]);                              \
            uint64_t b1 = mul2(E[2*s+1], ninv1);                              \
            E[2*s+1] = fma2(b1, E[2*s+1], E[2*s+1]);                          \
            uint64_t d0 = add2(a0, b0), d1 = add2(a1, b1);                    \
            ulonglong2* kp = reinterpret_cast<ulonglong2*>(                   \
                dynbuf + (KOFF) + s * 8192 + tid * 16);                       \
            if (WO) { ulonglong2 kv; kv.x = d0; kv.y = d1; *kp = kv; }        \
            else { ulonglong2 kv = *kp;                                       \
                   kv.x = add2(kv.x, d0); kv.y = add2(kv.y, d1); *kp = kv; }  \
            if (DOACC) {                                                      \
                accS = add2(accS, E[2*s]); accS = add2(accS, E[2*s+1]);       \
                accQ = fma2(E[2*s], E[2*s], accQ);                            \
                accQ = fma2(E[2*s+1], E[2*s+1], accQ);                        \
            }                                                                 \
        }                                                                     \
        if (DOACC) {                                                          \
            float h0, h1;                                                     \
            upk2(accS, h0, h1); (Sv) = h0 + h1;                               \
            upk2(accQ, h0, h1); (Qv) = h0 + h1;                               \
        }                                                                     \
    } while (0)

#define STORE(KOFF, orow)                                                     \
    do {                                                                      \
        _Pragma("unroll")                                                     \
        for (int s = 0; s < 8; s++) {                                         \
            float4 kv = *reinterpret_cast<const float4*>(                     \
                dynbuf + (KOFF) + s * 8192 + tid * 16);                       \
            float4 v;                                                         \
            v.x = -kv.x; v.y = -kv.y; v.z = -kv.z; v.w = -kv.w;               \
            *reinterpret_cast<float4*>((orow) + s * 2048 + tid * 4) = v;      \
        }                                                                     \
    } while (0)

__global__ void __launch_bounds__(NTH, 1)
subset_op_kernel(const float* __restrict__ scores,
                 const float* __restrict__ gnoise,
                 float* __restrict__ out) {
    __shared__ alignas(16) float2 redA[16], redB[16];
    __shared__ alignas(8) unsigned long long mA1_s, mA2_s, mB_s;

    const int tid = threadIdx.x;
    const int w = tid >> 5, l = tid & 31;
    const uint32_t mA1 = smem_u32(&mA1_s);
    const uint32_t mA2 = smem_u32(&mA2_s);
    const uint32_t mB  = smem_u32(&mB_s);
    const uint32_t kna32 = smem_u32(dynbuf + KNA);
    const uint32_t knb32 = smem_u32(dynbuf + KNB);
    const uint32_t stg32 = smem_u32(dynbuf + STG);

    const float c = 0.999999f;   // inv = c/sum keeps onehot < 1 (replaces EPS clamp)

    if (tid == 0) { mbar_init(mA1, 1); mbar_init(mA2, 1); mbar_init(mB, 1); }
    __syncthreads();

    uint64_t eA[16], eB[16];
    float SA, QA, SB, QB, i0A, i1A, i0B, i1B;
    uint64_t SnP, QnP;
    int pA1 = 0, pA2 = 0, pB = 0;

    // ---- prime: load + prologue row A0; then issue B0 waves ----
    int base = 2 * blockIdx.x;
    if (tid == 0) {
        const size_t ra = (size_t)base * NCOLS;
        mbar_expect_tx(mA1, 98304);
        bulk_g2s(stg32,         scores + ra, 49152, mA1);
        bulk_g2s(stg32 + 49152, gnoise + ra, 49152, mA1);
        mbar_expect_tx(mA2, 32768);
        bulk_g2s(kna32,         scores + ra + 12288, 16384, mA2);
        bulk_g2s(kna32 + 16384, gnoise + ra + 12288, 16384, mA2);
    }
    mbar_wait(mA1, pA1); pA1 ^= 1;
    mbar_wait(mA2, pA2); pA2 ^= 1;
    SnP = 0ULL; QnP = 0ULL;
    PROLOGUE(eA, KNA);
    { float h0, h1; upk2(SnP, h0, h1); SA = h0 + h1; upk2(QnP, h0, h1); QA = h0 + h1; }
    __syncthreads();   // stage + knA-head reads done
    if (tid == 0) {
        const size_t rbg = (size_t)(base + 1) * NCOLS;
        mbar_expect_tx(mB, 131072);
        bulk_g2s(stg32,         scores + rbg, 49152, mB);
        bulk_g2s(stg32 + 49152, gnoise + rbg, 49152, mB);
        bulk_g2s(knb32,         scores + rbg + 12288, 16384, mB);
        bulk_g2s(knb32 + 16384, gnoise + rbg + 12288, 16384, mB);
    }

    for (; base < BROWS; base += PAIRSTEP) {
        const bool has_next = (base + PAIRSTEP) < BROWS;
        const size_t raOut = (size_t)base * NCOLS;
        const size_t rbOut = (size_t)(base + 1) * NCOLS;

        // A slots 0-2 (B's TMA streams underneath)
        REDB(SA, QA, redA); REDE(redA, i0A, i1A); APPLY(eA, i0A, i1A, KNA, 1, 1, SA, QA);
        REDB(SA, QA, redA); REDE(redA, i0A, i1A); APPLY(eA, i0A, i1A, KNA, 0, 1, SA, QA);
        REDB(SA, QA, redA); REDE(redA, i0A, i1A); APPLY(eA, i0A, i1A, KNA, 0, 1, SA, QA);

        // B prologue
        mbar_wait(mB, pB); pB ^= 1;
        SnP = 0ULL; QnP = 0ULL;
        PROLOGUE(eB, KNB);
        { float h0, h1; upk2(SnP, h0, h1); SB = h0 + h1; upk2(QnP, h0, h1); QB = h0 + h1; }
        __syncthreads();   // stage reads done -> stage free for A'
        if (has_next && tid == 0) {
            const size_t na = (size_t)(base + PAIRSTEP) * NCOLS;
            mbar_expect_tx(mA1, 98304);
            bulk_g2s(stg32,         scores + na, 49152, mA1);
            bulk_g2s(stg32 + 49152, gnoise + na, 49152, mA1);
        }

        // interleaved ladder: A slots 3-7 and B slots 0-5, each row's APPLY
        // filling the other's reduction gap. (R16 bug: ladder was 2 rungs
        // short -> 14 of 16 iterations. Now: A RED@2,4,6,8,10 APPLY@3,5,7,9,11;
        // B RED@1,3,5,7,9,11 APPLY@2,4,6,8,10,12 -> 8 groups per row.)
        REDB(SB, QB, redB);                                          REDE(redB, i0B, i1B);
        REDB(SA, QA, redA); APPLY(eB, i0B, i1B, KNB, 1, 1, SB, QB);  REDE(redA, i0A, i1A);
        REDB(SB, QB, redB); APPLY(eA, i0A, i1A, KNA, 0, 1, SA, QA);  REDE(redB, i0B, i1B);
        REDB(SA, QA, redA); APPLY(eB, i0B, i1B, KNB, 0, 1, SB, QB);  REDE(redA, i0A, i1A);
        REDB(SB, QB, redB); APPLY(eA, i0A, i1A, KNA, 0, 1, SA, QA);  REDE(redB, i0B, i1B);
        REDB(SA, QA, redA); APPLY(eB, i0B, i1B, KNB, 0, 1, SB, QB);  REDE(redA, i0A, i1A);
        REDB(SB, QB, redB); APPLY(eA, i0A, i1A, KNA, 0, 1, SA, QA);  REDE(redB, i0B, i1B);
        REDB(SA, QA, redA); APPLY(eB, i0B, i1B, KNB, 0, 1, SB, QB);  REDE(redA, i0A, i1A);
        REDB(SB, QB, redB); APPLY(eA, i0A, i1A, KNA, 0, 1, SA, QA);  REDE(redB, i0B, i1B);
        REDB(SA, QA, redA); APPLY(eB, i0B, i1B, KNB, 0, 1, SB, QB);  REDE(redA, i0A, i1A);
        REDB(SB, QB, redB); APPLY(eA, i0A, i1A, KNA, 0, 0, SA, QA);  REDE(redB, i0B, i1B);
        // A slots 3-7 all applied (row A done); B slots 0-4 applied; i for B5 ready.

        // B tail: slots 5-7, with A store / prefetch as fillers
        APPLY(eB, i0B, i1B, KNB, 0, 1, SB, QB);          // B slot 5
        REDB(SB, QB, redB);
        STORE(KNA, out + raOut);                         // fills B6's red gap
        __syncthreads();                                 // knA reads done
        if (has_next && tid == 0) {
            const size_t na = (size_t)(base + PAIRSTEP) * NCOLS;
            mbar_expect_tx(mA2, 32768);
            bulk_g2s(kna32,         scores + na + 12288, 16384, mA2);
            bulk_g2s(kna32 + 16384, gnoise + na + 12288, 16384, mA2);
        }
        REDE(redB, i0B, i1B);
        APPLY(eB, i0B, i1B, KNB, 0, 1, SB, QB);          // B slot 6
        REDB(SB, QB, redB); REDE(redB, i0B, i1B);
        APPLY(eB, i0B, i1B, KNB, 0, 0, SB, QB);          // B slot 7

        // A' prologue (units 0-5 from stage, 6-7 from knA head)
        if (has_next) {
            mbar_wait(mA1, pA1); pA1 ^= 1;
            SnP = 0ULL; QnP = 0ULL;
            CONS(eA, 0, STG + 0,     STG + 49152 + 0);
            CONS(eA, 1, STG + 8192,  STG + 49152 + 8192);
            CONS(eA, 2, STG + 16384, STG + 49152 + 16384);
            CONS(eA, 3, STG + 24576, STG + 49152 + 24576);
            CONS(eA, 4, STG + 32768, STG + 49152 + 32768);
            CONS(eA, 5, STG + 40960, STG + 49152 + 40960);
            mbar_wait(mA2, pA2); pA2 ^= 1;
            CONS(eA, 6, KNA + 0,    KNA + 16384);
            CONS(eA, 7, KNA + 8192, KNA + 16384 + 8192);
            float h0, h1;
            upk2(SnP, h0, h1); SA = h0 + h1;
            upk2(QnP, h0, h1); QA = h0 + h1;
        }

        STORE(KNB, out + rbOut);
        __syncthreads();   // knB + stage reads done before B' waves land
        if (has_next && tid == 0) {
            const size_t nb = (size_t)(base + PAIRSTEP + 1) * NCOLS;
            mbar_expect_tx(mB, 131072);
            bulk_g2s(stg32,         scores + nb, 49152, mB);
            bulk_g2s(stg32 + 49152, gnoise + nb, 49152, mB);
            bulk_g2s(knb32,         scores + nb + 12288, 16384, mB);
            bulk_g2s(knb32 + 16384, gnoise + nb + 12288, 16384, mB);
        }
    }
}

extern "C" void kernel_launch(void* const* d_in, const int* in_sizes, int n_in,
                              void* d_out, int out_size) {
    const float* scores = (const float*)d_in[0];
    const float* g      = (const float*)d_in[1];
    float* out          = (float*)d_out;
    cudaFuncSetAttribute(subset_op_kernel,
                         cudaFuncAttributeMaxDynamicSharedMemorySize, DYN_SMEM);
    subset_op_kernel<<<GRID, NTH, DYN_SMEM>>>(scores, g, out);
}